// round 5
// baseline (speedup 1.0000x reference)
#include <cuda_runtime.h>
#include <math.h>

#define HW 65536

// ---------------- scratch (device globals; no allocation) ----------------
__device__ __align__(16) float g_sage[4 * 3 * HW];  // enc planes: mx, av, c1(+b1)
__device__ __align__(16) float g_sagd[4 * 3 * HW];  // dec planes: mx, av, c1(+b1)
__device__ __align__(16) float g_spat[4 * HW];      // sigmoid spatial gate
__device__ float g_encmean[4 * 128];
__device__ float g_encmax [4 * 128];
__device__ float g_decmean[4 * 256];
__device__ float g_decmax [4 * 256];
__device__ __align__(16) float g_ch[4 * 128];       // sigmoid channel gate

#define RATIO (127.0f / 255.0f)

// ================= encoder per-pixel planes =================
// grid (256, 4) x 256 threads: y = blockIdx.x, x = threadIdx.x, b = blockIdx.y
__global__ void __launch_bounds__(256) k_enc_pix(const float* __restrict__ xe,
                                                 const float* __restrict__ sw1e,
                                                 const float* __restrict__ sb1e) {
    __shared__ float sw[128];
    if (threadIdx.x < 128) sw[threadIdx.x] = sw1e[threadIdx.x];
    __syncthreads();
    const int x = threadIdx.x, y = blockIdx.x, b = blockIdx.y;
    const float* base = xe + (size_t)b * 128 * HW + y * 256 + x;
    float mx = -3.4e38f, sm = 0.f, dt = 0.f;
    for (int c = 0; c < 128; c++) {
        float v = base[(size_t)c * HW];
        mx = fmaxf(mx, v);
        sm += v;
        dt = fmaf(sw[c], v, dt);
    }
    const int p = y * 256 + x;
    const size_t eb = (size_t)b * 3 * HW;
    g_sage[eb + p]          = mx;
    g_sage[eb + HW + p]     = sm * (1.f / 128.f);
    g_sage[eb + 2 * HW + p] = dt + sb1e[0];
}

// ================= encoder per-channel stats (deterministic) =================
// grid (128, 4): c = blockIdx.x, b = blockIdx.y, 256 threads
__global__ void __launch_bounds__(256) k_enc_red(const float* __restrict__ xe) {
    __shared__ float ssum[256], smax[256];
    const int c = blockIdx.x, b = blockIdx.y, t = threadIdx.x;
    const float* p = xe + ((size_t)b * 128 + c) * HW;
    float s = 0.f, m = -3.4e38f;
    for (int i = t; i < HW; i += 256) {
        float v = p[i];
        s += v;
        m = fmaxf(m, v);
    }
    ssum[t] = s; smax[t] = m;
    __syncthreads();
    for (int o = 128; o > 0; o >>= 1) {
        if (t < o) {
            ssum[t] += ssum[t + o];
            smax[t] = fmaxf(smax[t], smax[t + o]);
        }
        __syncthreads();
    }
    if (t == 0) {
        g_encmean[b * 128 + c] = ssum[0] * (1.f / 65536.f);
        g_encmax [b * 128 + c] = smax[0];
    }
}

// ================= decoder per-pixel planes (smem row staging) =================
// grid (256, 4) x 256 threads: y = blockIdx.x, x = threadIdx.x, b = blockIdx.y
__global__ void __launch_bounds__(256) k_dec_pix(const float* __restrict__ xd,
                                                 const float* __restrict__ sw1d,
                                                 const float* __restrict__ sb1d) {
    __shared__ float sw[256];
    __shared__ float srow[256];   // [0:128) source row i0, [128:256) source row i1
    const int t = threadIdx.x, y = blockIdx.x, b = blockIdx.y;
    sw[t] = sw1d[t];
    float py = (float)y * RATIO;
    int i0 = min((int)floorf(py), 127), i1 = min(i0 + 1, 127);
    float wy = py - (float)i0;
    float px = (float)t * RATIO;
    int j0 = min((int)floorf(px), 127), j1 = min(j0 + 1, 127);
    float wx = px - (float)j0;
    const int half = t >> 7, lane = t & 127;
    const int goff = (half ? i1 : i0) * 128 + lane;
    const float* base = xd + (size_t)b * 256 * 16384;

    float mx = 0.f, sm = 0.f, dt = 0.f;
    for (int c = 0; c < 256; c++) {
        __syncthreads();                       // protect srow from prior reads
        srow[t] = base[(size_t)c * 16384 + goff];
        __syncthreads();
        float top = srow[j0]       * (1.f - wx) + srow[j1]       * wx;
        float bot = srow[128 + j0] * (1.f - wx) + srow[128 + j1] * wx;
        float v = top * (1.f - wy) + bot * wy;
        v = fmaxf(v, 0.f);
        mx = fmaxf(mx, v);
        sm += v;
        dt = fmaf(sw[c], v, dt);
    }
    const int p = y * 256 + t;
    const size_t db = (size_t)b * 3 * HW;
    g_sagd[db + p]          = mx;
    g_sagd[db + HW + p]     = sm * (1.f / 256.f);
    g_sagd[db + 2 * HW + p] = dt + sb1d[0];
}

// ================= decoder per-channel stats (deterministic, smem staging) =================
// grid (256, 4): c = blockIdx.x, b = blockIdx.y, 256 threads (thread = output column)
__global__ void __launch_bounds__(256) k_dec_red(const float* __restrict__ xd) {
    __shared__ float srow[256];
    __shared__ float ssum[256], smax[256];
    const int c = blockIdx.x, b = blockIdx.y, t = threadIdx.x;
    const float* pc = xd + ((size_t)b * 256 + c) * 16384;
    float px = (float)t * RATIO;
    int j0 = min((int)floorf(px), 127), j1 = min(j0 + 1, 127);
    float wx = px - (float)j0;
    const int half = t >> 7, lane = t & 127;

    float s = 0.f, m = 0.f;
    for (int y = 0; y < 256; y++) {
        float py = (float)y * RATIO;
        int i0 = min((int)floorf(py), 127), i1 = min(i0 + 1, 127);
        float wy = py - (float)i0;
        __syncthreads();
        srow[t] = pc[(half ? i1 : i0) * 128 + lane];
        __syncthreads();
        float top = srow[j0]       * (1.f - wx) + srow[j1]       * wx;
        float bot = srow[128 + j0] * (1.f - wx) + srow[128 + j1] * wx;
        float v = top * (1.f - wy) + bot * wy;
        v = fmaxf(v, 0.f);
        s += v;
        m = fmaxf(m, v);
    }
    __syncthreads();
    ssum[t] = s; smax[t] = m;
    __syncthreads();
    for (int o = 128; o > 0; o >>= 1) {
        if (t < o) {
            ssum[t] += ssum[t + o];
            smax[t] = fmaxf(smax[t], smax[t + o]);
        }
        __syncthreads();
    }
    if (t == 0) {
        g_decmean[b * 256 + c] = ssum[0] * (1.f / 65536.f);
        g_decmax [b * 256 + c] = smax[0];
    }
}

// ================= channel MLP =================
__global__ void k_mlp(const float* __restrict__ cwea, const float* __restrict__ cbea,
                      const float* __restrict__ cwem, const float* __restrict__ cbem,
                      const float* __restrict__ cwda, const float* __restrict__ cbda,
                      const float* __restrict__ cwdm, const float* __restrict__ cbdm,
                      const float* __restrict__ cwf,  const float* __restrict__ cbf) {
    __shared__ float tsm[64];
    const int t = threadIdx.x;   // 512 threads
    if (t < 64) {
        int b = t >> 4, n = t & 15;
        float acc = cbea[n] + cbem[n] + cbda[n] + cbdm[n];
        for (int c = 0; c < 128; c++)
            acc += g_encmean[b * 128 + c] * cwea[n * 128 + c]
                 + g_encmax [b * 128 + c] * cwem[n * 128 + c];
        for (int c = 0; c < 256; c++)
            acc += g_decmean[b * 256 + c] * cwda[n * 256 + c]
                 + g_decmax [b * 256 + c] * cwdm[n * 256 + c];
        tsm[t] = acc;
    }
    __syncthreads();
    int b = t >> 7, o = t & 127;
    float a = cbf[o];
#pragma unroll
    for (int n = 0; n < 16; n++) a = fmaf(tsm[b * 16 + n], cwf[o * 16 + n], a);
    g_ch[t] = 1.f / (1.f + __expf(-a));
}

// ================= fused 7x7 conv (6 planes) + sigmoid =================
// grid (16, 16, 4): 16x16 output tile, 256 threads, 1 output/thread
__global__ void __launch_bounds__(256) k_conv(const float* __restrict__ sw2e,
                                              const float* __restrict__ sw2d,
                                              const float* __restrict__ sb2e,
                                              const float* __restrict__ sb2d) {
    __shared__ float pl[6][22 * 22];
    __shared__ float wsm[294];
    __shared__ float bv;
    const int tid = threadIdx.x;
    const int X0 = blockIdx.x * 16, Y0 = blockIdx.y * 16, b = blockIdx.z;
    // FIX: 294 weights, 256 threads -> must loop (was `if (tid < 294)`, leaving
    // wsm[256..293] as uninitialized smem => nondeterministic ~0.5 rel_err)
    for (int i = tid; i < 294; i += 256)
        wsm[i] = (i < 147) ? sw2e[i] : sw2d[i - 147];
    if (tid == 0) bv = sb2e[0] + sb2d[0];
    const size_t eb = (size_t)b * 3 * HW;
    for (int idx = tid; idx < 22 * 22; idx += 256) {
        int ry = idx / 22, rx = idx - ry * 22;
        int gy = Y0 + ry - 3, gx = X0 + rx - 3;
        float v0 = 0, v1 = 0, v2 = 0, v3 = 0, v4 = 0, v5 = 0;
        if (gy >= 0 && gy < 256 && gx >= 0 && gx < 256) {
            int p = gy * 256 + gx;
            v0 = g_sage[eb + p];
            v1 = g_sage[eb + HW + p];
            v2 = g_sage[eb + 2 * HW + p];
            v3 = g_sagd[eb + p];
            v4 = g_sagd[eb + HW + p];
            v5 = g_sagd[eb + 2 * HW + p];
        }
        pl[0][idx] = v0; pl[1][idx] = v1; pl[2][idx] = v2;
        pl[3][idx] = v3; pl[4][idx] = v4; pl[5][idx] = v5;
    }
    __syncthreads();
    const int tx = tid & 15, ty = tid >> 4;
    float acc = bv;
    for (int pp = 0; pp < 6; pp++)
#pragma unroll
        for (int ky = 0; ky < 7; ky++)
#pragma unroll
            for (int kx = 0; kx < 7; kx++)
                acc = fmaf(pl[pp][(ty + ky) * 22 + tx + kx], wsm[pp * 49 + ky * 7 + kx], acc);
    g_spat[(size_t)b * HW + (Y0 + ty) * 256 + X0 + tx] = 1.f / (1.f + __expf(-acc));
}

// ================= final multiply =================
// grid (64, 512): blockIdx.y = b*128+c, float4 per thread
__global__ void __launch_bounds__(256) k_final(const float* __restrict__ xe,
                                               float* __restrict__ out) {
    const int bc = blockIdx.y;
    const int b  = bc >> 7;
    const int i  = blockIdx.x * 256 + threadIdx.x;
    const float s = g_ch[bc];
    float4 xv = reinterpret_cast<const float4*>(xe)[(size_t)bc * 16384 + i];
    float4 sp = reinterpret_cast<const float4*>(g_spat)[(size_t)b * 16384 + i];
    float4 o;
    o.x = xv.x * sp.x * s;
    o.y = xv.y * sp.y * s;
    o.z = xv.z * sp.z * s;
    o.w = xv.w * sp.w * s;
    reinterpret_cast<float4*>(out)[(size_t)bc * 16384 + i] = o;
}

// ================= launch =================
extern "C" void kernel_launch(void* const* d_in, const int* in_sizes, int n_in,
                              void* d_out, int out_size) {
    const float* xe   = (const float*)d_in[0];
    const float* xd   = (const float*)d_in[1];
    const float* cwea = (const float*)d_in[2];
    const float* cbea = (const float*)d_in[3];
    const float* cwem = (const float*)d_in[4];
    const float* cbem = (const float*)d_in[5];
    const float* cwda = (const float*)d_in[6];
    const float* cbda = (const float*)d_in[7];
    const float* cwdm = (const float*)d_in[8];
    const float* cbdm = (const float*)d_in[9];
    const float* cwf  = (const float*)d_in[10];
    const float* cbf  = (const float*)d_in[11];
    const float* sw1e = (const float*)d_in[12];
    const float* sb1e = (const float*)d_in[13];
    const float* sw2e = (const float*)d_in[14];
    const float* sb2e = (const float*)d_in[15];
    const float* sw1d = (const float*)d_in[16];
    const float* sb1d = (const float*)d_in[17];
    const float* sw2d = (const float*)d_in[18];
    const float* sb2d = (const float*)d_in[19];
    float* out = (float*)d_out;

    k_enc_pix<<<dim3(256, 4), 256>>>(xe, sw1e, sb1e);
    k_enc_red<<<dim3(128, 4), 256>>>(xe);
    k_dec_pix<<<dim3(256, 4), 256>>>(xd, sw1d, sb1d);
    k_dec_red<<<dim3(256, 4), 256>>>(xd);
    k_mlp<<<1, 512>>>(cwea, cbea, cwem, cbem, cwda, cbda, cwdm, cbdm, cwf, cbf);
    k_conv<<<dim3(16, 16, 4), 256>>>(sw2e, sw2d, sb2e, sb2d);
    k_final<<<dim3(64, 512), 256>>>(xe, out);
}